// round 8
// baseline (speedup 1.0000x reference)
#include <cuda_runtime.h>

typedef unsigned long long ULL;
typedef unsigned int uint;

constexpr int B    = 512;
constexpr int T    = 2048;
constexpr int H    = 64;
constexpr int NB   = 2;        // batch elements per block
constexpr int NBLK = B / NB;   // 256 blocks -> 2 independent blocks per SM
constexpr int NGT  = 128;      // gate threads: 2 gates each (cls0:(i,g), cls1:(f,o))
constexpr int NTHR = NGT + 32; // + 1 layer-2 warp = 160

__device__ __forceinline__ ULL pack2(float x, float y) {
    ULL r; asm("mov.b64 %0, {%1, %2};" : "=l"(r) : "f"(x), "f"(y)); return r;
}
__device__ __forceinline__ void unpack2(ULL v, float& x, float& y) {
    asm("mov.b64 {%0, %1}, %2;" : "=f"(x), "=f"(y) : "l"(v));
}
__device__ __forceinline__ ULL ffma2(ULL a, ULL b, ULL c) {
    ULL d; asm("fma.rn.f32x2 %0, %1, %2, %3;" : "=l"(d) : "l"(a), "l"(b), "l"(c)); return d;
}
__device__ __forceinline__ float fsigm(float x) {
    return __fdividef(1.f, 1.f + __expf(-x));
}
__device__ __forceinline__ float ftanh(float x) {
    return __fdividef(2.f, 1.f + __expf(-2.f * x)) - 1.f;
}

__global__ __launch_bounds__(NTHR, 2)   // force 2 blocks co-resident per SM
void lstm2_kernel(const float* __restrict__ x,
                  const float* __restrict__ Wih1,
                  const float* __restrict__ Whh1,
                  const float* __restrict__ bih1,
                  const float* __restrict__ bhh1,
                  const float* __restrict__ Wih2,
                  const float* __restrict__ Whh2,
                  const float* __restrict__ bih2,
                  const float* __restrict__ bhh2,
                  float* __restrict__ out)
{
    // x pre-duplicated {x,x} per batch: xsd[t][b] is a f32x2 pair (32KB)
    __shared__ __align__(16) ULL   xsd[T][NB];
    // h pre-duplicated: hdup[buf][k] = {h_k,h_k (b0), h_k,h_k (b1)} 16B
    __shared__ __align__(16) float hdup[2][H][4];
    __shared__ __align__(16) float c1buf[2][H][NB];  // c1 for layer 2

    const int tid = threadIdx.x;
    const int b0  = blockIdx.x * NB;

    // ---- one-time preload ----
    #pragma unroll
    for (int bl = 0; bl < NB; bl++)
        for (int t = tid; t < T; t += NTHR) {
            float v = x[(b0 + bl) * T + t];
            xsd[t][bl] = pack2(v, v);
        }
    for (int i = tid; i < 2 * H * 4; i += NTHR)
        (&hdup[0][0][0])[i] = 0.f;
    for (int i = tid; i < 2 * H * NB; i += NTHR)
        (&c1buf[0][0][0])[i] = 0.f;

    const bool is_gate = tid < NGT;

    // gate mapping: cls = tid&1 (0:(i,g), 1:(f,o)), j = tid>>1 (unit 0..63)
    ULL ww[H];
    ULL wx = 0, bb = 0;
    int cls = 0, j = 0;
    float c1s0 = 0.f, c1s1 = 0.f;   // cls1 holds c for both batches
    if (is_gate) {
        cls = tid & 1;
        j   = tid >> 1;
        const int gA = (cls ? H : 0) + j;          // i or f
        const int gB = (cls ? 3 * H : 2 * H) + j;  // g or o
        #pragma unroll
        for (int k = 0; k < H; k++)
            ww[k] = pack2(Whh1[gA * H + k], Whh1[gB * H + k]);
        wx = pack2(Wih1[gA], Wih1[gB]);
        bb = pack2(bih1[gA] + bhh1[gA], bih1[gB] + bhh1[gB]);
    }

    // layer-2 warp (tid in [128,160)): lane l: bl=l>>4, qq=(l>>2)&3, seg=(l&3)*16
    float w2[16];
    float whh2q = 0.f, b2q = 0.f, h2v = 0.f, c2 = 0.f;
    const int l = tid - NGT;
    int bl2 = 0, ks = 0;
    if (!is_gate) {
        bl2 = l >> 4;
        const int qq = (l >> 2) & 3;
        ks = (l & 3) * 16;
        #pragma unroll
        for (int jj = 0; jj < 16; jj++) w2[jj] = Wih2[qq * H + ks + jj];
        whh2q = Whh2[qq];
        b2q   = bih2[qq] + bhh2[qq];
    }
    __syncthreads();

    for (int t = 0; t <= T; t++) {
        const int wb = t & 1;       // write buffer
        const int rb = wb ^ 1;      // read buffer (h of t-1)
        if (is_gate) {
            if (t < T) {
                ULL acc0 = ffma2(wx, xsd[t][0], bb);  // batch 0: {A,B}
                ULL acc1 = ffma2(wx, xsd[t][1], bb);  // batch 1: {A,B}
                #pragma unroll
                for (int k = 0; k < H; k++) {
                    // broadcast 16B: {h_k,h_k (b0), h_k,h_k (b1)}
                    ulonglong2 hv =
                        *reinterpret_cast<const ulonglong2*>(&hdup[rb][k][0]);
                    acc0 = ffma2(ww[k], hv.x, acc0);
                    acc1 = ffma2(ww[k], hv.y, acc1);
                }
                float A0, B0, A1, B1;
                unpack2(acc0, A0, B0);
                unpack2(acc1, A1, B1);
                // A (i or f) -> sigmoid; B: cls0 g -> tanh, cls1 o -> sigmoid
                A0 = fsigm(A0); A1 = fsigm(A1);
                const bool isg = (cls == 0);
                {
                    float s0 = fsigm(isg ? 2.f * B0 : B0);
                    float s1 = fsigm(isg ? 2.f * B1 : B1);
                    B0 = isg ? 2.f * s0 - 1.f : s0;
                    B1 = isg ? 2.f * s1 - 1.f : s1;
                }
                // cls0 sends p_b = sigm(i)*tanh(g) to partner lane (xor 1)
                float p0 = A0 * B0;
                float p1 = A1 * B1;
                p0 = __shfl_xor_sync(0xffffffffu, p0, 1);
                p1 = __shfl_xor_sync(0xffffffffu, p1, 1);
                if (cls) {   // owner of c: A=sigm(f), B=sigm(o)
                    c1s0 = fmaf(A0, c1s0, p0);
                    c1s1 = fmaf(A1, c1s1, p1);
                    float h0 = B0 * ftanh(c1s0);
                    float h1 = B1 * ftanh(c1s1);
                    *reinterpret_cast<float4*>(&hdup[wb][j][0]) =
                        make_float4(h0, h0, h1, h1);
                    *reinterpret_cast<float2*>(&c1buf[wb][j][0]) =
                        make_float2(c1s0, c1s1);
                }
            }
        } else if (t > 0) {
            // layer 2 consumes c1 of step t-1 (one step behind)
            const float* cb = &c1buf[(t + 1) & 1][0][0];
            float s = 0.f;
            #pragma unroll
            for (int jj = 0; jj < 16; jj++)
                s = fmaf(cb[(ks + jj) * NB + bl2], w2[jj], s);
            s += __shfl_xor_sync(0xffffffffu, s, 1);
            s += __shfl_xor_sync(0xffffffffu, s, 2);
            const float gate = s + b2q + h2v * whh2q;
            const int base = l & 16;
            const float gi = __shfl_sync(0xffffffffu, gate, base + 0);
            const float gf = __shfl_sync(0xffffffffu, gate, base + 4);
            const float gg = __shfl_sync(0xffffffffu, gate, base + 8);
            const float go = __shfl_sync(0xffffffffu, gate, base + 12);
            c2  = fsigm(gf) * c2 + fsigm(gi) * ftanh(gg);
            h2v = fsigm(go) * ftanh(c2);
            if ((l & 15) == 0)
                out[(b0 + bl2) * T + (t - 1)] = c2;
        }
        __syncthreads();  // single barrier per step (h double-buffered)
    }
}

extern "C" void kernel_launch(void* const* d_in, const int* in_sizes, int n_in,
                              void* d_out, int out_size) {
    (void)in_sizes; (void)n_in; (void)out_size;
    lstm2_kernel<<<NBLK, NTHR>>>(
        (const float*)d_in[0],  // x
        (const float*)d_in[1],  // Wih1
        (const float*)d_in[2],  // Whh1
        (const float*)d_in[3],  // bih1
        (const float*)d_in[4],  // bhh1
        (const float*)d_in[5],  // Wih2
        (const float*)d_in[6],  // Whh2
        (const float*)d_in[7],  // bih2
        (const float*)d_in[8],  // bhh2
        (float*)d_out);
}

// round 10
// speedup vs baseline: 1.0009x; 1.0009x over previous
#include <cuda_runtime.h>

typedef unsigned long long ULL;
typedef unsigned int uint;

constexpr int B    = 512;
constexpr int T    = 2048;
constexpr int H    = 64;
constexpr int NB   = 4;        // batch elements per block (2 per group)
constexpr int NBLK = B / NB;   // 128 blocks, 1 per SM
constexpr int GSZ  = 160;      // threads per group (5 warps)
constexpr int NTHR = 2 * GSZ;  // 320

__device__ __forceinline__ ULL pack2(float x, float y) {
    ULL r; asm("mov.b64 %0, {%1, %2};" : "=l"(r) : "f"(x), "f"(y)); return r;
}
__device__ __forceinline__ void unpack2(ULL v, float& x, float& y) {
    asm("mov.b64 {%0, %1}, %2;" : "=f"(x), "=f"(y) : "l"(v));
}
__device__ __forceinline__ ULL ffma2(ULL a, ULL b, ULL c) {
    ULL d; asm("fma.rn.f32x2 %0, %1, %2, %3;" : "=l"(d) : "l"(a), "l"(b), "l"(c)); return d;
}
__device__ __forceinline__ float fsigm(float x) {
    return __fdividef(1.f, 1.f + __expf(-x));
}
__device__ __forceinline__ float ftanh(float x) {
    return __fdividef(2.f, 1.f + __expf(-2.f * x)) - 1.f;
}
__device__ __forceinline__ void group_bar(int id) {
    asm volatile("bar.sync %0, %1;" :: "r"(id), "r"(GSZ) : "memory");
}

__global__ __launch_bounds__(NTHR, 1)
void lstm2_kernel(const float* __restrict__ x,
                  const float* __restrict__ Wih1,
                  const float* __restrict__ Whh1,
                  const float* __restrict__ bih1,
                  const float* __restrict__ bhh1,
                  const float* __restrict__ Wih2,
                  const float* __restrict__ Whh2,
                  const float* __restrict__ bih2,
                  const float* __restrict__ bhh2,
                  float* __restrict__ out)
{
    __shared__ __align__(16) float xs[T][NB];           // 32KB input stage
    // per-group h, duplicated {h_b0,h_b0,h_b1,h_b1}, double-buffered
    __shared__ __align__(16) float hdup[2][2][H][4];    // [grp][buf][k][4]
    __shared__ __align__(16) float c1buf[2][2][H][2];   // [grp][buf][j][batch]

    const int tid = threadIdx.x;
    const int b0  = blockIdx.x * NB;
    const int grp = tid / GSZ;         // warps 0-4 -> grp0, 5-9 -> grp1
    const int lg  = tid - grp * GSZ;   // 0..159 within group

    // ---- one-time preload ----
    #pragma unroll
    for (int bl = 0; bl < NB; bl++)
        for (int t = tid; t < T; t += NTHR)
            xs[t][bl] = x[(b0 + bl) * T + t];
    for (int i = tid; i < 2 * 2 * H * 4; i += NTHR)
        (&hdup[0][0][0][0])[i] = 0.f;
    for (int i = tid; i < 2 * 2 * H * 2; i += NTHR)
        (&c1buf[0][0][0][0])[i] = 0.f;

    const bool is_gate = lg < 128;

    // gate mapping: cls = lg&1 (0:(i,g), 1:(f,o)), j = lg>>1 (unit 0..63)
    ULL ww[H];
    ULL wx = 0, bb = 0;
    int cls = 0, j = 0;
    float c1s0 = 0.f, c1s1 = 0.f;      // cls1 holds c for the 2 batches
    if (is_gate) {
        cls = lg & 1;
        j   = lg >> 1;
        const int gA = (cls ? H : 0) + j;          // i or f
        const int gB = (cls ? 3 * H : 2 * H) + j;  // g or o
        #pragma unroll
        for (int k = 0; k < H; k++)
            ww[k] = pack2(Whh1[gA * H + k], Whh1[gB * H + k]);
        wx = pack2(Wih1[gA], Wih1[gB]);
        bb = pack2(bih1[gA] + bhh1[gA], bih1[gB] + bhh1[gB]);
    }

    // layer-2 warp of each group (lg in [128,160)):
    // lane l: bl = l>>4 (batch within group), qq = (l>>2)&3, seg = (l&3)*16
    float w2[16];
    float whh2q = 0.f, b2q = 0.f, h2v = 0.f, c2 = 0.f;
    const int l = lg - 128;
    int bl2 = 0, ks = 0;
    if (!is_gate) {
        bl2 = l >> 4;
        const int qq = (l >> 2) & 3;
        ks = (l & 3) * 16;
        #pragma unroll
        for (int jj = 0; jj < 16; jj++) w2[jj] = Wih2[qq * H + ks + jj];
        whh2q = Whh2[qq];
        b2q   = bih2[qq] + bhh2[qq];
    }
    __syncthreads();   // one block-wide sync; after this, groups run free

    const int barid = 1 + grp;
    for (int t = 0; t <= T; t++) {
        const int wb = t & 1;       // write buffer
        const int rb = wb ^ 1;      // read buffer (h of t-1)
        if (is_gate) {
            if (t < T) {
                // x for this group's 2 batches
                float2 xv = *reinterpret_cast<const float2*>(&xs[t][2 * grp]);
                ULL acc0 = ffma2(wx, pack2(xv.x, xv.x), bb);  // batch 0: {A,B}
                ULL acc1 = ffma2(wx, pack2(xv.y, xv.y), bb);  // batch 1: {A,B}
                #pragma unroll
                for (int k = 0; k < H; k++) {
                    ulonglong2 hv = *reinterpret_cast<const ulonglong2*>(
                        &hdup[grp][rb][k][0]);
                    acc0 = ffma2(ww[k], hv.x, acc0);
                    acc1 = ffma2(ww[k], hv.y, acc1);
                }
                float A0, B0, A1, B1;
                unpack2(acc0, A0, B0);
                unpack2(acc1, A1, B1);
                // A (i or f) -> sigmoid; B: cls0 g -> tanh, cls1 o -> sigmoid
                A0 = fsigm(A0); A1 = fsigm(A1);
                const bool isg = (cls == 0);
                {
                    float s0 = fsigm(isg ? 2.f * B0 : B0);
                    float s1 = fsigm(isg ? 2.f * B1 : B1);
                    B0 = isg ? 2.f * s0 - 1.f : s0;
                    B1 = isg ? 2.f * s1 - 1.f : s1;
                }
                // cls0 sends p_b = sigm(i)*tanh(g) to partner lane (xor 1)
                float p0 = A0 * B0;
                float p1 = A1 * B1;
                p0 = __shfl_xor_sync(0xffffffffu, p0, 1);
                p1 = __shfl_xor_sync(0xffffffffu, p1, 1);
                if (cls) {   // owner of c: A=sigm(f), B=sigm(o)
                    c1s0 = fmaf(A0, c1s0, p0);
                    c1s1 = fmaf(A1, c1s1, p1);
                    float h0 = B0 * ftanh(c1s0);
                    float h1 = B1 * ftanh(c1s1);
                    *reinterpret_cast<float4*>(&hdup[grp][wb][j][0]) =
                        make_float4(h0, h0, h1, h1);
                    *reinterpret_cast<float2*>(&c1buf[grp][wb][j][0]) =
                        make_float2(c1s0, c1s1);
                }
            }
        } else if (t > 0) {
            // layer 2 consumes c1 of step t-1 (one step behind)
            const float* cb = &c1buf[grp][(t + 1) & 1][0][0];
            float s = 0.f;
            #pragma unroll
            for (int jj = 0; jj < 16; jj++)
                s = fmaf(cb[(ks + jj) * 2 + bl2], w2[jj], s);
            s += __shfl_xor_sync(0xffffffffu, s, 1);
            s += __shfl_xor_sync(0xffffffffu, s, 2);
            const float gate = s + b2q + h2v * whh2q;
            const int base = l & 16;
            const float gi = __shfl_sync(0xffffffffu, gate, base + 0);
            const float gf = __shfl_sync(0xffffffffu, gate, base + 4);
            const float gg = __shfl_sync(0xffffffffu, gate, base + 8);
            const float go = __shfl_sync(0xffffffffu, gate, base + 12);
            c2  = fsigm(gf) * c2 + fsigm(gi) * ftanh(gg);
            h2v = fsigm(go) * ftanh(c2);
            if ((l & 15) == 0)
                out[(b0 + 2 * grp + bl2) * T + (t - 1)] = c2;
        }
        group_bar(barid);   // per-group barrier: groups drift independently
    }
}

extern "C" void kernel_launch(void* const* d_in, const int* in_sizes, int n_in,
                              void* d_out, int out_size) {
    (void)in_sizes; (void)n_in; (void)out_size;
    lstm2_kernel<<<NBLK, NTHR>>>(
        (const float*)d_in[0],  // x
        (const float*)d_in[1],  // Wih1
        (const float*)d_in[2],  // Whh1
        (const float*)d_in[3],  // bih1
        (const float*)d_in[4],  // bhh1
        (const float*)d_in[5],  // Wih2
        (const float*)d_in[6],  // Whh2
        (const float*)d_in[7],  // bih2
        (const float*)d_in[8],  // bhh2
        (float*)d_out);
}

// round 11
// speedup vs baseline: 1.4155x; 1.4142x over previous
#include <cuda_runtime.h>

typedef unsigned long long ULL;
typedef unsigned int uint;

constexpr int B    = 512;
constexpr int T    = 2048;
constexpr int H    = 64;
constexpr int NB   = 4;        // batch elements per block
constexpr int NBLK = B / NB;   // 128 blocks, 1 per SM
constexpr int NTHR = 320;      // 8 gate warps + 2 layer-2 warps

__device__ __forceinline__ ULL pack2(float x, float y) {
    ULL r; asm("mov.b64 %0, {%1, %2};" : "=l"(r) : "f"(x), "f"(y)); return r;
}
__device__ __forceinline__ void unpack2(ULL v, float& x, float& y) {
    asm("mov.b64 {%0, %1}, %2;" : "=f"(x), "=f"(y) : "l"(v));
}
__device__ __forceinline__ ULL ffma2(ULL a, ULL b, ULL c) {
    ULL d; asm("fma.rn.f32x2 %0, %1, %2, %3;" : "=l"(d) : "l"(a), "l"(b), "l"(c)); return d;
}
__device__ __forceinline__ float fsigm(float x) {
    return __fdividef(1.f, 1.f + __expf(-x));
}
__device__ __forceinline__ float ftanh(float x) {
    return __fdividef(2.f, 1.f + __expf(-2.f * x)) - 1.f;
}

__global__ __launch_bounds__(NTHR, 1)
void lstm2_kernel(const float* __restrict__ x,
                  const float* __restrict__ Wih1,
                  const float* __restrict__ Whh1,
                  const float* __restrict__ bih1,
                  const float* __restrict__ bhh1,
                  const float* __restrict__ Wih2,
                  const float* __restrict__ Whh2,
                  const float* __restrict__ bih2,
                  const float* __restrict__ bhh2,
                  float* __restrict__ out)
{
    __shared__ __align__(16) float xs[T][NB];        // 32KB input stage
    __shared__ __align__(16) float hrow[2][NB][H];   // h1, k-contiguous per batch
    __shared__ __align__(16) float c1b[2][NB][H];    // c1, k-contiguous per batch

    const int tid  = threadIdx.x;
    const int b0   = blockIdx.x * NB;
    const int wid  = tid >> 5;
    const int lane = tid & 31;

    // ---- one-time preload ----
    #pragma unroll
    for (int bl = 0; bl < NB; bl++)
        for (int t = tid; t < T; t += NTHR)
            xs[t][bl] = x[(b0 + bl) * T + t];
    for (int i = tid; i < 2 * NB * H; i += NTHR) {
        (&hrow[0][0][0])[i] = 0.f;
        (&c1b[0][0][0])[i]  = 0.f;
    }

    const bool is_gate = wid < 8;

    // gate mapping: bp = wid>>2 (warp-uniform batch pair), j = unit, cls = lane&1
    // cls0 owns (i_j, g_j); cls1 owns (f_j, o_j). Weights k-paired {w_2m, w_2m+1}.
    ULL wwA[32], wwB[32];
    float wiA = 0.f, wiB = 0.f, bA = 0.f, bB = 0.f;
    int bp = 0, j = 0, cls = 0;
    float c1s0 = 0.f, c1s1 = 0.f;   // cls1: c for batches 2bp, 2bp+1
    if (is_gate) {
        bp  = wid >> 2;
        j   = ((wid & 3) << 4) | (lane >> 1);
        cls = lane & 1;
        const int gA = (cls ? H : 0) + j;          // i or f
        const int gB = (cls ? 3 * H : 2 * H) + j;  // g or o
        #pragma unroll
        for (int m = 0; m < 32; m++) {
            wwA[m] = pack2(Whh1[gA * H + 2 * m], Whh1[gA * H + 2 * m + 1]);
            wwB[m] = pack2(Whh1[gB * H + 2 * m], Whh1[gB * H + 2 * m + 1]);
        }
        wiA = Wih1[gA]; wiB = Wih1[gB];
        bA  = bih1[gA] + bhh1[gA];
        bB  = bih1[gB] + bhh1[gB];
    }

    // layer-2 warps (wid 8,9): l in 0..63: bl2=l>>4, qq=(l>>2)&3, ks=(l&3)*16
    float w2[16];
    float whh2q = 0.f, b2q = 0.f, h2v = 0.f, c2 = 0.f;
    const int l = tid - 256;
    int bl2 = 0, ks = 0;
    if (!is_gate) {
        bl2 = l >> 4;
        const int qq = (l >> 2) & 3;
        ks = (l & 3) * 16;
        #pragma unroll
        for (int jj = 0; jj < 16; jj++) w2[jj] = Wih2[qq * H + ks + jj];
        whh2q = Whh2[qq];
        b2q   = bih2[qq] + bhh2[qq];
    }
    __syncthreads();

    for (int t = 0; t <= T; t++) {
        const int wb = t & 1;       // write buffer
        const int rb = wb ^ 1;      // read buffer (h of t-1)
        if (is_gate) {
            if (t < T) {
                // input + bias seed (scalar), packed into lo half of each chain
                float2 xv = *reinterpret_cast<const float2*>(&xs[t][2 * bp]);
                ULL aA0 = pack2(fmaf(wiA, xv.x, bA), 0.f);
                ULL aA1 = pack2(fmaf(wiA, xv.y, bA), 0.f);
                ULL aB0 = pack2(fmaf(wiB, xv.x, bB), 0.f);
                ULL aB1 = pack2(fmaf(wiB, xv.y, bB), 0.f);
                const float* h0p = &hrow[rb][2 * bp][0];
                const float* h1p = &hrow[rb][2 * bp + 1][0];
                #pragma unroll
                for (int m = 0; m < 16; m++) {
                    // 2 broadcast LDS.128: 4 k-values per batch
                    ulonglong2 hv0 =
                        *reinterpret_cast<const ulonglong2*>(h0p + 4 * m);
                    ulonglong2 hv1 =
                        *reinterpret_cast<const ulonglong2*>(h1p + 4 * m);
                    aA0 = ffma2(wwA[2 * m],     hv0.x, aA0);
                    aB0 = ffma2(wwB[2 * m],     hv0.x, aB0);
                    aA1 = ffma2(wwA[2 * m],     hv1.x, aA1);
                    aB1 = ffma2(wwB[2 * m],     hv1.x, aB1);
                    aA0 = ffma2(wwA[2 * m + 1], hv0.y, aA0);
                    aB0 = ffma2(wwB[2 * m + 1], hv0.y, aB0);
                    aA1 = ffma2(wwA[2 * m + 1], hv1.y, aA1);
                    aB1 = ffma2(wwB[2 * m + 1], hv1.y, aB1);
                }
                // horizontal fold: lo (even k) + hi (odd k)
                float A0, A1, B0, B1, lo, hi;
                unpack2(aA0, lo, hi); A0 = lo + hi;
                unpack2(aA1, lo, hi); A1 = lo + hi;
                unpack2(aB0, lo, hi); B0 = lo + hi;
                unpack2(aB1, lo, hi); B1 = lo + hi;
                // A (i or f) -> sigmoid; B: cls0 g -> tanh, cls1 o -> sigmoid
                A0 = fsigm(A0); A1 = fsigm(A1);
                const bool isg = (cls == 0);
                {
                    float s0 = fsigm(isg ? 2.f * B0 : B0);
                    float s1 = fsigm(isg ? 2.f * B1 : B1);
                    B0 = isg ? 2.f * s0 - 1.f : s0;
                    B1 = isg ? 2.f * s1 - 1.f : s1;
                }
                // cls0 sends p_b = sigm(i)*tanh(g) to partner (lane xor 1)
                float p0 = A0 * B0;
                float p1 = A1 * B1;
                p0 = __shfl_xor_sync(0xffffffffu, p0, 1);
                p1 = __shfl_xor_sync(0xffffffffu, p1, 1);
                if (cls) {   // owner of c: A=sigm(f), B=sigm(o)
                    c1s0 = fmaf(A0, c1s0, p0);
                    c1s1 = fmaf(A1, c1s1, p1);
                    hrow[wb][2 * bp][j]     = B0 * ftanh(c1s0);
                    hrow[wb][2 * bp + 1][j] = B1 * ftanh(c1s1);
                    c1b[wb][2 * bp][j]      = c1s0;
                    c1b[wb][2 * bp + 1][j]  = c1s1;
                }
            }
        } else if (t > 0) {
            // layer 2 consumes c1 of step t-1 (one step behind)
            const float* cbp = &c1b[(t + 1) & 1][bl2][ks];
            float4 q0 = *reinterpret_cast<const float4*>(cbp + 0);
            float4 q1 = *reinterpret_cast<const float4*>(cbp + 4);
            float4 q2 = *reinterpret_cast<const float4*>(cbp + 8);
            float4 q3 = *reinterpret_cast<const float4*>(cbp + 12);
            float s = q0.x * w2[0] + q0.y * w2[1] + q0.z * w2[2] + q0.w * w2[3]
                    + q1.x * w2[4] + q1.y * w2[5] + q1.z * w2[6] + q1.w * w2[7]
                    + q2.x * w2[8] + q2.y * w2[9] + q2.z * w2[10] + q2.w * w2[11]
                    + q3.x * w2[12] + q3.y * w2[13] + q3.z * w2[14] + q3.w * w2[15];
            s += __shfl_xor_sync(0xffffffffu, s, 1);
            s += __shfl_xor_sync(0xffffffffu, s, 2);
            const float gate = s + b2q + h2v * whh2q;
            const int lane2 = l & 31;
            const int base  = lane2 & 16;
            const float gi = __shfl_sync(0xffffffffu, gate, base + 0);
            const float gf = __shfl_sync(0xffffffffu, gate, base + 4);
            const float gg = __shfl_sync(0xffffffffu, gate, base + 8);
            const float go = __shfl_sync(0xffffffffu, gate, base + 12);
            c2  = fsigm(gf) * c2 + fsigm(gi) * ftanh(gg);
            h2v = fsigm(go) * ftanh(c2);
            if ((lane2 & 15) == 0)
                out[(b0 + bl2) * T + (t - 1)] = c2;
        }
        __syncthreads();  // single barrier per step
    }
}

extern "C" void kernel_launch(void* const* d_in, const int* in_sizes, int n_in,
                              void* d_out, int out_size) {
    (void)in_sizes; (void)n_in; (void)out_size;
    lstm2_kernel<<<NBLK, NTHR>>>(
        (const float*)d_in[0],  // x
        (const float*)d_in[1],  // Wih1
        (const float*)d_in[2],  // Whh1
        (const float*)d_in[3],  // bih1
        (const float*)d_in[4],  // bhh1
        (const float*)d_in[5],  // Wih2
        (const float*)d_in[6],  // Whh2
        (const float*)d_in[7],  // bih2
        (const float*)d_in[8],  // bhh2
        (float*)d_out);
}

// round 14
// speedup vs baseline: 1.4641x; 1.0343x over previous
#include <cuda_runtime.h>

typedef unsigned long long ULL;
typedef unsigned int uint;

constexpr int B     = 512;
constexpr int T     = 2048;
constexpr int H     = 64;
constexpr int NB    = 4;       // batch elements per block
constexpr int NBLK  = B / NB;  // 128 blocks
constexpr int NGT   = 256;     // gate threads: lane = (j&7)*4 + q
constexpr int NTHR  = NGT + 64;// + 2 layer-2 warps = 320
constexpr int WARM  = 256;     // chunk-1 warmup steps (state contraction)
constexpr int NSTEP = 1152;    // per-chunk steps: chunk0=[0,1152), chunk1=[896,2048)
constexpr int CH1S  = NSTEP - WARM;  // 896: chunk1 global start

__device__ __forceinline__ ULL pack2(float x, float y) {
    ULL r; asm("mov.b64 %0, {%1, %2};" : "=l"(r) : "f"(x), "f"(y)); return r;
}
__device__ __forceinline__ void unpack2(ULL v, float& x, float& y) {
    asm("mov.b64 {%0, %1}, %2;" : "=f"(x), "=f"(y) : "l"(v));
}
__device__ __forceinline__ ULL ffma2(ULL a, ULL b, ULL c) {
    ULL d; asm("fma.rn.f32x2 %0, %1, %2, %3;" : "=l"(d) : "l"(a), "l"(b), "l"(c)); return d;
}
__device__ __forceinline__ float fsigm(float x) {
    return __fdividef(1.f, 1.f + __expf(-x));
}
__device__ __forceinline__ float ftanh(float x) {
    return __fdividef(2.f, 1.f + __expf(-2.f * x)) - 1.f;
}

__global__ __launch_bounds__(NTHR, 1)
void lstm2_kernel(const float* __restrict__ x,
                  const float* __restrict__ Wih1,
                  const float* __restrict__ Whh1,
                  const float* __restrict__ bih1,
                  const float* __restrict__ bhh1,
                  const float* __restrict__ Wih2,
                  const float* __restrict__ Whh2,
                  const float* __restrict__ bih2,
                  const float* __restrict__ bhh2,
                  float* __restrict__ out)
{
    __shared__ __align__(16) float xs[T][NB];           // 32KB full input
    __shared__ __align__(16) float h2s[2][2][H][NB];    // [chunk][buf][k][batch]
    __shared__ __align__(16) float c1buf[2][2][H][NB];  // [chunk][buf][j][batch]

    const int tid = threadIdx.x;
    const int b0  = blockIdx.x * NB;

    // ---- one-time preload ----
    #pragma unroll
    for (int bl = 0; bl < NB; bl++)
        for (int t = tid; t < T; t += NTHR)
            xs[t][bl] = x[(b0 + bl) * T + t];
    for (int i = tid; i < 2 * 2 * H * NB; i += NTHR)
        (&h2s[0][0][0][0])[i] = 0.f;

    const bool is_gate = tid < NGT;

    // gate mapping (R4-proven): q = tid&3 (gate 0=i,1=f,2=g,3=o), j = tid>>2
    ULL ww[H];
    ULL wxp = 0, bp = 0;
    int q = 0;
    bool isg = false;
    float c1A = 0.f, c1B = 0.f;   // cell state: chunk0, chunk1 (unit j, batch q)
    if (is_gate) {
        q = tid & 3;
        const int j = tid >> 2;
        const int g = q * H + j;   // torch gate-row order i,f,g,o
        isg = (q == 2);
        #pragma unroll
        for (int k = 0; k < H; k++) {
            float w = Whh1[g * H + k];
            ww[k] = pack2(w, w);
        }
        float wi = Wih1[g];
        wxp = pack2(wi, wi);
        float bb = bih1[g] + bhh1[g];
        bp = pack2(bb, bb);
    }

    // layer-2 threads (tid in [256,320)): (bl, gate qq, k-segment of 16),
    // each handles BOTH chunks sequentially per step.
    float w2[16];
    float whh2q = 0.f, b2q = 0.f;
    float h2v[2] = {0.f, 0.f}, c2v[2] = {0.f, 0.f};
    const int l = tid - NGT;
    int bl2 = 0, ks = 0;
    if (!is_gate) {
        bl2 = l >> 4;
        const int qq = (l >> 2) & 3;
        ks = (l & 3) * 16;
        #pragma unroll
        for (int jj = 0; jj < 16; jj++) w2[jj] = Wih2[qq * H + ks + jj];
        whh2q = Whh2[qq];
        b2q   = bih2[qq] + bhh2[qq];
    }
    __syncthreads();

    for (int s = 0; s <= NSTEP; s++) {
        const int wb = s & 1;       // write buffer
        const int rb = wb ^ 1;      // read buffer (h of prev step)
        if (is_gate) {
            if (s < NSTEP) {
                // chunk0: global t = s; chunk1: global t = CH1S + s
                ULL xA01 = *reinterpret_cast<const ULL*>(&xs[s][0]);
                ULL xA23 = *reinterpret_cast<const ULL*>(&xs[s][2]);
                ULL xB01 = *reinterpret_cast<const ULL*>(&xs[CH1S + s][0]);
                ULL xB23 = *reinterpret_cast<const ULL*>(&xs[CH1S + s][2]);
                ULL aA0 = ffma2(wxp, xA01, bp);
                ULL aA1 = ffma2(wxp, xA23, bp);
                ULL aB0 = ffma2(wxp, xB01, bp);
                ULL aB1 = ffma2(wxp, xB23, bp);
                #pragma unroll
                for (int k = 0; k < H; k++) {
                    ulonglong2 hA =
                        *reinterpret_cast<const ulonglong2*>(&h2s[0][rb][k][0]);
                    ulonglong2 hB =
                        *reinterpret_cast<const ulonglong2*>(&h2s[1][rb][k][0]);
                    aA0 = ffma2(ww[k], hA.x, aA0);
                    aB0 = ffma2(ww[k], hB.x, aB0);
                    aA1 = ffma2(ww[k], hA.y, aA1);
                    aB1 = ffma2(ww[k], hB.y, aB1);
                }
                float vA0, vA1, vA2, vA3, vB0, vB1, vB2, vB3;
                unpack2(aA0, vA0, vA1); unpack2(aA1, vA2, vA3);
                unpack2(aB0, vB0, vB1); unpack2(aB1, vB2, vB3);
                // branchless activation: tanh(x) = 2*sigmoid(2x)-1
                {
                    float s0 = fsigm(isg ? 2.f * vA0 : vA0);
                    float s1 = fsigm(isg ? 2.f * vA1 : vA1);
                    float s2 = fsigm(isg ? 2.f * vA2 : vA2);
                    float s3 = fsigm(isg ? 2.f * vA3 : vA3);
                    float s4 = fsigm(isg ? 2.f * vB0 : vB0);
                    float s5 = fsigm(isg ? 2.f * vB1 : vB1);
                    float s6 = fsigm(isg ? 2.f * vB2 : vB2);
                    float s7 = fsigm(isg ? 2.f * vB3 : vB3);
                    vA0 = isg ? 2.f * s0 - 1.f : s0;
                    vA1 = isg ? 2.f * s1 - 1.f : s1;
                    vA2 = isg ? 2.f * s2 - 1.f : s2;
                    vA3 = isg ? 2.f * s3 - 1.f : s3;
                    vB0 = isg ? 2.f * s4 - 1.f : s4;
                    vB1 = isg ? 2.f * s5 - 1.f : s5;
                    vB2 = isg ? 2.f * s6 - 1.f : s6;
                    vB3 = isg ? 2.f * s7 - 1.f : s7;
                }
                // quad transpose (R4-proven), both chunks interleaved
                {
                    float a_ = ((q & 1) == 0) ? vA1 : vA0;
                    float b_ = ((q & 1) == 0) ? vA3 : vA2;
                    float c_ = ((q & 1) == 0) ? vB1 : vB0;
                    float d_ = ((q & 1) == 0) ? vB3 : vB2;
                    a_ = __shfl_xor_sync(0xffffffffu, a_, 1);
                    b_ = __shfl_xor_sync(0xffffffffu, b_, 1);
                    c_ = __shfl_xor_sync(0xffffffffu, c_, 1);
                    d_ = __shfl_xor_sync(0xffffffffu, d_, 1);
                    if ((q & 1) == 0) { vA1 = a_; vA3 = b_; vB1 = c_; vB3 = d_; }
                    else              { vA0 = a_; vA2 = b_; vB0 = c_; vB2 = d_; }
                    float e_ = ((q & 2) == 0) ? vA2 : vA0;
                    float f_ = ((q & 2) == 0) ? vA3 : vA1;
                    float g_ = ((q & 2) == 0) ? vB2 : vB0;
                    float h_ = ((q & 2) == 0) ? vB3 : vB1;
                    e_ = __shfl_xor_sync(0xffffffffu, e_, 2);
                    f_ = __shfl_xor_sync(0xffffffffu, f_, 2);
                    g_ = __shfl_xor_sync(0xffffffffu, g_, 2);
                    h_ = __shfl_xor_sync(0xffffffffu, h_, 2);
                    if ((q & 2) == 0) { vA2 = e_; vA3 = f_; vB2 = g_; vB3 = h_; }
                    else              { vA0 = e_; vA1 = f_; vB0 = g_; vB1 = h_; }
                }
                // lane q now holds (unit j, batch q): v0=i v1=f v2=tanh(g) v3=o
                const int j = tid >> 2;
                c1A = fmaf(vA1, c1A, vA0 * vA2);
                c1B = fmaf(vB1, c1B, vB0 * vB2);
                float hA = vA3 * ftanh(c1A);
                float hB = vB3 * ftanh(c1B);
                h2s[0][wb][j][q]   = hA;
                h2s[1][wb][j][q]   = hB;
                c1buf[0][wb][j][q] = c1A;
                c1buf[1][wb][j][q] = c1B;
            }
        } else if (s > 0) {
            // layer 2, one step behind, both chunks
            #pragma unroll
            for (int ch = 0; ch < 2; ch++) {
                const float* cb = &c1buf[ch][(s + 1) & 1][0][0];
                float sa = 0.f;
                #pragma unroll
                for (int jj = 0; jj < 16; jj++)
                    sa = fmaf(cb[(ks + jj) * NB + bl2], w2[jj], sa);
                sa += __shfl_xor_sync(0xffffffffu, sa, 1);
                sa += __shfl_xor_sync(0xffffffffu, sa, 2);
                const float gate = sa + b2q + h2v[ch] * whh2q;
                const int lane = l & 31;
                const int base = lane & 16;
                const float gi = __shfl_sync(0xffffffffu, gate, base + 0);
                const float gf = __shfl_sync(0xffffffffu, gate, base + 4);
                const float gg = __shfl_sync(0xffffffffu, gate, base + 8);
                const float go = __shfl_sync(0xffffffffu, gate, base + 12);
                c2v[ch] = fsigm(gf) * c2v[ch] + fsigm(gi) * ftanh(gg);
                h2v[ch] = fsigm(go) * ftanh(c2v[ch]);
                const int tg = (ch ? CH1S : 0) + (s - 1);
                const bool emit = ch ? (s - 1 >= WARM) : true;
                if (((lane & 15) == 0) && emit)
                    out[(b0 + bl2) * T + tg] = c2v[ch];
            }
        }
        __syncthreads();  // single barrier per step (both chunks)
    }
}

extern "C" void kernel_launch(void* const* d_in, const int* in_sizes, int n_in,
                              void* d_out, int out_size) {
    (void)in_sizes; (void)n_in; (void)out_size;
    lstm2_kernel<<<NBLK, NTHR>>>(
        (const float*)d_in[0],  // x
        (const float*)d_in[1],  // Wih1
        (const float*)d_in[2],  // Whh1
        (const float*)d_in[3],  // bih1
        (const float*)d_in[4],  // bhh1
        (const float*)d_in[5],  // Wih2
        (const float*)d_in[6],  // Whh2
        (const float*)d_in[7],  // bih2
        (const float*)d_in[8],  // bhh2
        (float*)d_out);
}

// round 15
// speedup vs baseline: 1.5664x; 1.0699x over previous
#include <cuda_runtime.h>
#include <cuda_bf16.h>

typedef unsigned int uint;

constexpr int B    = 512;
constexpr int T    = 2048;
constexpr int H    = 64;
constexpr int NB   = 4;
constexpr int NBLK = B / NB;   // 128 blocks, 1/SM
constexpr int NTHR = 160;      // 4 mma warps + 1 layer-2 warp

__device__ __forceinline__ float fsigm(float x) {
    return __fdividef(1.f, 1.f + __expf(-x));
}
__device__ __forceinline__ float ftanh(float x) {
    return __fdividef(2.f, 1.f + __expf(-2.f * x)) - 1.f;
}
__device__ __forceinline__ uint pack_bf2(float e0, float e1) {
    unsigned short u0 = __bfloat16_as_ushort(__float2bfloat16(e0));
    unsigned short u1 = __bfloat16_as_ushort(__float2bfloat16(e1));
    return (uint)u0 | ((uint)u1 << 16);
}
__device__ __forceinline__ void mma16816(float& c0, float& c1, float& c2, float& c3,
                                         uint a0, uint a1, uint a2, uint a3,
                                         uint b0, uint b1) {
    asm volatile(
        "mma.sync.aligned.m16n8k16.row.col.f32.bf16.bf16.f32 "
        "{%0,%1,%2,%3}, {%4,%5,%6,%7}, {%8,%9}, {%0,%1,%2,%3};"
        : "+f"(c0), "+f"(c1), "+f"(c2), "+f"(c3)
        : "r"(a0), "r"(a1), "r"(a2), "r"(a3), "r"(b0), "r"(b1));
}

__global__ __launch_bounds__(NTHR, 1)
void lstm2_kernel(const float* __restrict__ x,
                  const float* __restrict__ Wih1,
                  const float* __restrict__ Whh1,
                  const float* __restrict__ bih1,
                  const float* __restrict__ bhh1,
                  const float* __restrict__ Wih2,
                  const float* __restrict__ Whh2,
                  const float* __restrict__ bih2,
                  const float* __restrict__ bhh2,
                  float* __restrict__ out)
{
    __shared__ __align__(16) float xs[T][NB];               // 32KB input
    // h as bf16 hi/lo, [buf][n(8)][72] padded: B-frag loads conflict-free
    __shared__ __align__(16) __nv_bfloat16 hbh[2][8][72];
    __shared__ __align__(16) __nv_bfloat16 hbl[2][8][72];
    __shared__ __align__(16) float c1b[2][NB][H];           // c1 for layer 2

    const int tid  = threadIdx.x;
    const int wid  = tid >> 5;
    const int lane = tid & 31;
    const int b0g  = blockIdx.x * NB;

    // ---- one-time preload ----
    for (int bl = 0; bl < NB; bl++)
        for (int t = tid; t < T; t += NTHR)
            xs[t][bl] = x[(b0g + bl) * T + t];
    for (int i = tid; i < 2 * 8 * 72; i += NTHR) {
        (&hbh[0][0][0])[i] = __float2bfloat16(0.f);
        (&hbl[0][0][0])[i] = __float2bfloat16(0.f);
    }

    const bool is_gate = wid < 4;
    const int  lq = lane >> 2;   // fragment group (unit-low / B-col)
    const int  m  = lane & 3;    // fragment thread-in-group
    const int  u0 = wid * 16 + lq;
    const int  u1 = u0 + 8;
    const bool real = (m < 2);   // C cols 2m,2m+1 are real batches iff m<2

    // A fragments: Whh1 bf16 hi/lo, 4 gate-tiles x 4 k-tiles x 4 regs
    uint Ahi[4][4][4], Alo[4][4][4];
    float wiA[4][2], bsA[4][2];
    float cst[4] = {0.f, 0.f, 0.f, 0.f};  // c1 state: (u0,b0),(u0,b1),(u1,b0),(u1,b1)
    if (is_gate) {
        #pragma unroll
        for (int q = 0; q < 4; q++) {
            #pragma unroll
            for (int kt = 0; kt < 4; kt++) {
                const int r0 = q * 64 + wid * 16 + lq;
                const int c0 = kt * 16 + 2 * m;
                #pragma unroll
                for (int e = 0; e < 4; e++) {
                    const int r = r0 + (e & 1) * 8;
                    const int c = c0 + (e >> 1) * 8;
                    float v0 = Whh1[r * H + c];
                    float v1 = Whh1[r * H + c + 1];
                    __nv_bfloat16 h0 = __float2bfloat16(v0);
                    __nv_bfloat16 h1 = __float2bfloat16(v1);
                    Ahi[q][kt][e] = ((uint)__bfloat16_as_ushort(h1) << 16) |
                                    __bfloat16_as_ushort(h0);
                    Alo[q][kt][e] = pack_bf2(v0 - __bfloat162float(h0),
                                             v1 - __bfloat162float(h1));
                }
            }
            wiA[q][0] = Wih1[q * H + u0];
            wiA[q][1] = Wih1[q * H + u1];
            bsA[q][0] = bih1[q * H + u0] + bhh1[q * H + u0];
            bsA[q][1] = bih1[q * H + u1] + bhh1[q * H + u1];
        }
    }

    // layer-2 warp (wid 4): lane: bl2=lane>>3, qq=(lane>>1)&3, koff=(lane&1)*32
    float w2[32];
    float whh2q = 0.f, b2q = 0.f, h2v = 0.f, c2v = 0.f;
    int bl2 = 0, koff = 0;
    if (!is_gate) {
        bl2  = lane >> 3;
        const int qq = (lane >> 1) & 3;
        koff = (lane & 1) * 32;
        #pragma unroll
        for (int jj = 0; jj < 32; jj++) w2[jj] = Wih2[qq * H + koff + jj];
        whh2q = Whh2[qq];
        b2q   = bih2[qq] + bhh2[qq];
    }
    __syncthreads();

    for (int t = 0; t <= T; t++) {
        const int wb = t & 1;
        const int rb = wb ^ 1;
        if (is_gate) {
            if (t < T) {
                // ---- B fragments from h(t-1): 16 conflict-free LDS.32 ----
                uint bh[4][2], blo[4][2];
                const __nv_bfloat16* ph = &hbh[rb][lq][0];
                const __nv_bfloat16* pl = &hbl[rb][lq][0];
                #pragma unroll
                for (int kt = 0; kt < 4; kt++) {
                    bh[kt][0]  = *(const uint*)(ph + kt * 16 + 2 * m);
                    bh[kt][1]  = *(const uint*)(ph + kt * 16 + 2 * m + 8);
                    blo[kt][0] = *(const uint*)(pl + kt * 16 + 2 * m);
                    blo[kt][1] = *(const uint*)(pl + kt * 16 + 2 * m + 8);
                }
                // ---- C init = bias + Wih*x (fp32 exact) ----
                float xb0 = 0.f, xb1 = 0.f;
                if (real) { xb0 = xs[t][2 * m]; xb1 = xs[t][2 * m + 1]; }
                float C[4][4];
                #pragma unroll
                for (int q = 0; q < 4; q++) {
                    C[q][0] = fmaf(wiA[q][0], xb0, bsA[q][0]);
                    C[q][1] = fmaf(wiA[q][0], xb1, bsA[q][0]);
                    C[q][2] = fmaf(wiA[q][1], xb0, bsA[q][1]);
                    C[q][3] = fmaf(wiA[q][1], xb1, bsA[q][1]);
                }
                // ---- 48 HMMA: Whi*Bhi + Whi*Blo + Wlo*Bhi ----
                #pragma unroll
                for (int kt = 0; kt < 4; kt++)
                    #pragma unroll
                    for (int q = 0; q < 4; q++)
                        mma16816(C[q][0], C[q][1], C[q][2], C[q][3],
                                 Ahi[q][kt][0], Ahi[q][kt][1], Ahi[q][kt][2],
                                 Ahi[q][kt][3], bh[kt][0], bh[kt][1]);
                #pragma unroll
                for (int kt = 0; kt < 4; kt++)
                    #pragma unroll
                    for (int q = 0; q < 4; q++)
                        mma16816(C[q][0], C[q][1], C[q][2], C[q][3],
                                 Ahi[q][kt][0], Ahi[q][kt][1], Ahi[q][kt][2],
                                 Ahi[q][kt][3], blo[kt][0], blo[kt][1]);
                #pragma unroll
                for (int kt = 0; kt < 4; kt++)
                    #pragma unroll
                    for (int q = 0; q < 4; q++)
                        mma16816(C[q][0], C[q][1], C[q][2], C[q][3],
                                 Alo[q][kt][0], Alo[q][kt][1], Alo[q][kt][2],
                                 Alo[q][kt][3], bh[kt][0], bh[kt][1]);
                // ---- epilogue: gates of unit u live in this lane ----
                #pragma unroll
                for (int c = 0; c < 4; c++) {
                    float gi = fsigm(C[0][c]);
                    float gf = fsigm(C[1][c]);
                    float gg = ftanh(C[2][c]);
                    float go = fsigm(C[3][c]);
                    cst[c] = fmaf(gf, cst[c], gi * gg);
                    float hv = go * ftanh(cst[c]);
                    if (real) {
                        const int u = (c >= 2) ? u1 : u0;
                        const int b = 2 * m + (c & 1);
                        __nv_bfloat16 hh = __float2bfloat16(hv);
                        hbh[wb][b][u] = hh;
                        hbl[wb][b][u] =
                            __float2bfloat16(hv - __bfloat162float(hh));
                        c1b[wb][b][u] = cst[c];
                    }
                }
            }
        } else if (t > 0) {
            // layer 2 consumes c1 of step t-1
            const float* cb = &c1b[(t + 1) & 1][bl2][koff];
            float4 q0 = *reinterpret_cast<const float4*>(cb + 0);
            float4 q1 = *reinterpret_cast<const float4*>(cb + 4);
            float4 q2 = *reinterpret_cast<const float4*>(cb + 8);
            float4 q3 = *reinterpret_cast<const float4*>(cb + 12);
            float4 q4 = *reinterpret_cast<const float4*>(cb + 16);
            float4 q5 = *reinterpret_cast<const float4*>(cb + 20);
            float4 q6 = *reinterpret_cast<const float4*>(cb + 24);
            float4 q7 = *reinterpret_cast<const float4*>(cb + 28);
            float s =
                q0.x*w2[0]+q0.y*w2[1]+q0.z*w2[2]+q0.w*w2[3]
              + q1.x*w2[4]+q1.y*w2[5]+q1.z*w2[6]+q1.w*w2[7]
              + q2.x*w2[8]+q2.y*w2[9]+q2.z*w2[10]+q2.w*w2[11]
              + q3.x*w2[12]+q3.y*w2[13]+q3.z*w2[14]+q3.w*w2[15]
              + q4.x*w2[16]+q4.y*w2[17]+q4.z*w2[18]+q4.w*w2[19]
              + q5.x*w2[20]+q5.y*w2[21]+q5.z*w2[22]+q5.w*w2[23]
              + q6.x*w2[24]+q6.y*w2[25]+q6.z*w2[26]+q6.w*w2[27]
              + q7.x*w2[28]+q7.y*w2[29]+q7.z*w2[30]+q7.w*w2[31];
            s += __shfl_xor_sync(0xffffffffu, s, 1);
            const float gate = s + b2q + h2v * whh2q;
            const int base = lane & ~7;
            const float gi = __shfl_sync(0xffffffffu, gate, base + 0);
            const float gf = __shfl_sync(0xffffffffu, gate, base + 2);
            const float gg = __shfl_sync(0xffffffffu, gate, base + 4);
            const float go = __shfl_sync(0xffffffffu, gate, base + 6);
            c2v = fsigm(gf) * c2v + fsigm(gi) * ftanh(gg);
            h2v = fsigm(go) * ftanh(c2v);
            if ((lane & 7) == 0)
                out[(b0g + bl2) * T + (t - 1)] = c2v;
        }
        __syncthreads();  // single barrier per step
    }
}

extern "C" void kernel_launch(void* const* d_in, const int* in_sizes, int n_in,
                              void* d_out, int out_size) {
    (void)in_sizes; (void)n_in; (void)out_size;
    lstm2_kernel<<<NBLK, NTHR>>>(
        (const float*)d_in[0],  // x
        (const float*)d_in[1],  // Wih1
        (const float*)d_in[2],  // Whh1
        (const float*)d_in[3],  // bih1
        (const float*)d_in[4],  // bhh1
        (const float*)d_in[5],  // Wih2
        (const float*)d_in[6],  // Whh2
        (const float*)d_in[7],  // bih2
        (const float*)d_in[8],  // bhh2
        (float*)d_out);
}